// round 11
// baseline (speedup 1.0000x reference)
#include <cuda_runtime.h>

#define N 8192
#define F 128
#define ALPHA 0.2f
#define PRO_BLOCKS 148
#define PRO_WARPS (PRO_BLOCKS * 32)

// Allocation-free scratch
__device__ float g_si[N];
__device__ float g_sj[N];

// Prologue (R9, unchanged): one wave (148 x 1024), vi/vj loads issued first,
// 'a' loaded directly, Wa via one shared round-trip.
__global__ __launch_bounds__(1024) void prologue_kernel(
    const float* __restrict__ vi, const float* __restrict__ vj,
    const float* __restrict__ W, const float* __restrict__ a) {
#if __CUDA_ARCH__ >= 900
    cudaTriggerProgrammaticLaunchCompletion();
#endif
    __shared__ float sWa1[F];
    __shared__ float sWa2[F];

    const int tid = threadIdx.x;
    const int lane = tid & 31;
    const int wid = tid >> 5;

    const int row0 = blockIdx.x * 32 + wid;
    const int row1 = row0 + PRO_WARPS;
    const bool has1 = (row1 < N);
    float4 x1a = reinterpret_cast<const float4*>(vi + (size_t)row0 * F)[lane];
    float4 x2a = reinterpret_cast<const float4*>(vj + (size_t)row0 * F)[lane];
    float4 x1b = make_float4(0.f, 0.f, 0.f, 0.f);
    float4 x2b = make_float4(0.f, 0.f, 0.f, 0.f);
    if (has1) {
        x1b = reinterpret_cast<const float4*>(vi + (size_t)row1 * F)[lane];
        x2b = reinterpret_cast<const float4*>(vj + (size_t)row1 * F)[lane];
    }

    const float4 a1v = reinterpret_cast<const float4*>(a)[lane];
    const float4 a2v = reinterpret_cast<const float4*>(a)[32 + lane];

#pragma unroll
    for (int r = 0; r < 4; ++r) {
        const int row = wid * 4 + r;
        float4 wv = reinterpret_cast<const float4*>(W + row * F)[lane];
        float s1 = fmaf(wv.x, a1v.x, fmaf(wv.y, a1v.y, fmaf(wv.z, a1v.z, wv.w * a1v.w)));
        float s2 = fmaf(wv.x, a2v.x, fmaf(wv.y, a2v.y, fmaf(wv.z, a2v.z, wv.w * a2v.w)));
#pragma unroll
        for (int o = 16; o > 0; o >>= 1) {
            s1 += __shfl_xor_sync(0xffffffffu, s1, o);
            s2 += __shfl_xor_sync(0xffffffffu, s2, o);
        }
        if (lane == 0) { sWa1[row] = s1; sWa2[row] = s2; }
    }
    __syncthreads();

    const float4 a1 = reinterpret_cast<const float4*>(sWa1)[lane];
    const float4 a2 = reinterpret_cast<const float4*>(sWa2)[lane];
    {
        float s1 = fmaf(x1a.x, a1.x, fmaf(x1a.y, a1.y, fmaf(x1a.z, a1.z, x1a.w * a1.w)));
        float s2 = fmaf(x2a.x, a2.x, fmaf(x2a.y, a2.y, fmaf(x2a.z, a2.z, x2a.w * a2.w)));
#pragma unroll
        for (int o = 16; o > 0; o >>= 1) {
            s1 += __shfl_down_sync(0xffffffffu, s1, o);
            s2 += __shfl_down_sync(0xffffffffu, s2, o);
        }
        if (lane == 0) { g_si[row0] = s1; g_sj[row0] = s2; }
    }
    if (has1) {
        float s1 = fmaf(x1b.x, a1.x, fmaf(x1b.y, a1.y, fmaf(x1b.z, a1.z, x1b.w * a1.w)));
        float s2 = fmaf(x2b.x, a2.x, fmaf(x2b.y, a2.y, fmaf(x2b.z, a2.z, x2b.w * a2.w)));
#pragma unroll
        for (int o = 16; o > 0; o >>= 1) {
            s1 += __shfl_down_sync(0xffffffffu, s1, o);
            s2 += __shfl_down_sync(0xffffffffu, s2, o);
        }
        if (lane == 0) { g_si[row1] = s1; g_sj[row1] = s2; }
    }
}

// Softmax: 2 rows per 512-thread block (grid 4096). sj loaded ONCE per j for
// both rows. Inner element math identical to the frozen R6/R7 form.
__global__ __launch_bounds__(512, 3) void softmax_pair_kernel(
    const int* __restrict__ adj, float* __restrict__ out) {
    __shared__ float red0[16];
    __shared__ float red1[16];
    __shared__ float bc0, bc1;

    const int r0 = blockIdx.x * 2;
    const int r1 = r0 + 1;
    const int tid = threadIdx.x;
    const int lane = tid & 31;
    const int wid = tid >> 5;

    const int4* adjA = reinterpret_cast<const int4*>(adj + (size_t)r0 * N);
    const int4* adjB = reinterpret_cast<const int4*>(adj + (size_t)r1 * N);
    const float4* sj4 = reinterpret_cast<const float4*>(g_sj);
    float4* outA = reinterpret_cast<float4*>(out + (size_t)r0 * N);
    float4* outB = reinterpret_cast<float4*>(out + (size_t)r1 * N);

    if (blockIdx.x < 888) {   // ~2 resident waves can overlap the prologue
#pragma unroll
        for (int it = 0; it < 4; ++it) {
            asm volatile("prefetch.global.L2 [%0];" :: "l"(adjA + tid + it * 512));
            asm volatile("prefetch.global.L2 [%0];" :: "l"(adjB + tid + it * 512));
        }
    }
#if __CUDA_ARCH__ >= 900
    cudaGridDependencySynchronize();
#endif

    const float si0 = g_si[r0];
    const float si1 = g_si[r1];
    float4 pregA[4], pregB[4];
    float lsum0 = 0.f, lsum1 = 0.f;
#pragma unroll
    for (int it = 0; it < 4; ++it) {
        const int j = tid + it * 512;
        int4   av0 = __ldcs(&adjA[j]);
        int4   av1 = __ldcs(&adjB[j]);
        float4 sj = sj4[j];
        float4 p;
        float t;
        t = si0 + sj.x; t = t > 0.f ? t : ALPHA * t; p.x = av0.x > 0 ? __expf(t) : 0.f;
        t = si0 + sj.y; t = t > 0.f ? t : ALPHA * t; p.y = av0.y > 0 ? __expf(t) : 0.f;
        t = si0 + sj.z; t = t > 0.f ? t : ALPHA * t; p.z = av0.z > 0 ? __expf(t) : 0.f;
        t = si0 + sj.w; t = t > 0.f ? t : ALPHA * t; p.w = av0.w > 0 ? __expf(t) : 0.f;
        pregA[it] = p;
        lsum0 += (p.x + p.y) + (p.z + p.w);
        t = si1 + sj.x; t = t > 0.f ? t : ALPHA * t; p.x = av1.x > 0 ? __expf(t) : 0.f;
        t = si1 + sj.y; t = t > 0.f ? t : ALPHA * t; p.y = av1.y > 0 ? __expf(t) : 0.f;
        t = si1 + sj.z; t = t > 0.f ? t : ALPHA * t; p.z = av1.z > 0 ? __expf(t) : 0.f;
        t = si1 + sj.w; t = t > 0.f ? t : ALPHA * t; p.w = av1.w > 0 ? __expf(t) : 0.f;
        pregB[it] = p;
        lsum1 += (p.x + p.y) + (p.z + p.w);
    }
#pragma unroll
    for (int o = 16; o > 0; o >>= 1) {
        lsum0 += __shfl_xor_sync(0xffffffffu, lsum0, o);
        lsum1 += __shfl_xor_sync(0xffffffffu, lsum1, o);
    }
    if (lane == 0) { red0[wid] = lsum0; red1[wid] = lsum1; }
    __syncthreads();
    if (wid == 0) {
        float s = (lane < 16) ? red0[lane] : 0.f;
#pragma unroll
        for (int o = 8; o > 0; o >>= 1)
            s += __shfl_xor_sync(0xffffffffu, s, o);
        if (lane == 0) bc0 = 1.0f / s;
    } else if (wid == 1) {
        float s = (lane < 16) ? red1[lane] : 0.f;
#pragma unroll
        for (int o = 8; o > 0; o >>= 1)
            s += __shfl_xor_sync(0xffffffffu, s, o);
        if (lane == 0) bc1 = 1.0f / s;
    }
    __syncthreads();
    const float inv0 = bc0;
    const float inv1 = bc1;

#pragma unroll
    for (int it = 0; it < 4; ++it) {
        const int j = tid + it * 512;
        float4 p = pregA[it];
        p.x *= inv0; p.y *= inv0; p.z *= inv0; p.w *= inv0;
        __stcs(&outA[j], p);
        float4 q = pregB[it];
        q.x *= inv1; q.y *= inv1; q.z *= inv1; q.w *= inv1;
        __stcs(&outB[j], q);
    }
}

extern "C" void kernel_launch(void* const* d_in, const int* in_sizes, int n_in,
                              void* d_out, int out_size) {
    const float* v_i = (const float*)d_in[0];
    const float* v_j = (const float*)d_in[1];
    const int*   adj = (const int*)d_in[2];
    const float* W   = (const float*)d_in[3];
    const float* a   = (const float*)d_in[4];
    float* out = (float*)d_out;

    prologue_kernel<<<PRO_BLOCKS, 1024>>>(v_i, v_j, W, a);

    cudaLaunchConfig_t cfg = {};
    cfg.gridDim = dim3(N / 2, 1, 1);
    cfg.blockDim = dim3(512, 1, 1);
    cfg.dynamicSmemBytes = 0;
    cfg.stream = 0;
    cudaLaunchAttribute attrs[1];
    attrs[0].id = cudaLaunchAttributeProgrammaticStreamSerialization;
    attrs[0].val.programmaticStreamSerializationAllowed = 1;
    cfg.attrs = attrs;
    cfg.numAttrs = 1;
    cudaLaunchKernelEx(&cfg, softmax_pair_kernel, adj, out);
}